// round 12
// baseline (speedup 1.0000x reference)
#include <cuda_runtime.h>
#include <cstdint>

#define NMAX 100000
#define EMAX 1600000
#define H 64

typedef unsigned long long u64;

// ---------------- device scratch (no allocations allowed) ----------------
__device__ float g_bufA[NMAX * H];
__device__ float g_bufB[NMAX * H];
__device__ float g_A2t[64 * 384];  // A2 tf32-rounded, layout [64][384] (B[k][n])
__device__ float g_A1t[64 * 64];   // A1 tf32-rounded, layout [64][64]  (B[k][n])
__device__ float g_deg[NMAX];      // degree, then dinv = rsqrt(deg)
__device__ int   g_cnt[NMAX];      // in-degree (edge count) histogram
__device__ int   g_off[NMAX + 1];  // CSR offsets by target node
__device__ int   g_cur[NMAX];      // scatter cursors
__device__ int2  g_epack[EMAX];    // (src_row, bitcast(norm)) grouped by target
__device__ int   g_bsum[128];      // scan block sums

// ---------------- packed f32x2 FMA helpers (sm_103a FFMA2) ----------------
__device__ __forceinline__ u64 pack2(float a) {
    u64 r;
    unsigned int u = __float_as_uint(a);
    asm("mov.b64 %0, {%1, %1};" : "=l"(r) : "r"(u));
    return r;
}
#define FMA2(d, a, b) asm("fma.rn.f32x2 %0, %1, %2, %0;" : "+l"(d) : "l"(a), "l"(b))

__device__ __forceinline__ void unpack2(u64 v, float& lo, float& hi) {
    unsigned int l, h;
    asm("mov.b64 {%0, %1}, %2;" : "=r"(l), "=r"(h) : "l"(v));
    lo = __uint_as_float(l);
    hi = __uint_as_float(h);
}

__device__ __forceinline__ float to_tf32(float x) {
    unsigned int u;
    asm("cvt.rna.tf32.f32 %0, %1;" : "=r"(u) : "f"(x));
    return __uint_as_float(u);
}
__device__ __forceinline__ unsigned to_tf32_u(float x) {
    unsigned int u;
    asm("cvt.rna.tf32.f32 %0, %1;" : "=r"(u) : "f"(x));
    return u;
}

// warp-level tf32 MMA (sm_80+ baseline feature, valid for compute_103)
__device__ __forceinline__ void mma_tf32(float c[4], const unsigned a[4],
                                         const unsigned b[2]) {
    asm volatile(
        "mma.sync.aligned.m16n8k8.row.col.f32.tf32.tf32.f32 "
        "{%0,%1,%2,%3}, {%4,%5,%6,%7}, {%8,%9}, {%0,%1,%2,%3};"
        : "+f"(c[0]), "+f"(c[1]), "+f"(c[2]), "+f"(c[3])
        : "r"(a[0]), "r"(a[1]), "r"(a[2]), "r"(a[3]), "r"(b[0]), "r"(b[1]));
}

// ---------------- degree / CSR build ----------------
__global__ void k_init(int n) {
    int i = blockIdx.x * blockDim.x + threadIdx.x;
    if (i < n) { g_deg[i] = 1.0f; g_cnt[i] = 0; }   // self-loop weight 1
}

__global__ void k_count(const int* __restrict__ col, const float* __restrict__ ew, int e) {
    int i = blockIdx.x * blockDim.x + threadIdx.x;
    if (i < e) {
        int c = col[i];
        atomicAdd(&g_deg[c], ew[i]);
        atomicAdd(&g_cnt[c], 1);
    }
}

__global__ void k_scan1(int n) {
    __shared__ int s[1024];
    int i = blockIdx.x * 1024 + threadIdx.x;
    int v = (i < n) ? g_cnt[i] : 0;
    s[threadIdx.x] = v;
    __syncthreads();
    #pragma unroll
    for (int o = 1; o < 1024; o <<= 1) {
        int t = (threadIdx.x >= o) ? s[threadIdx.x - o] : 0;
        __syncthreads();
        s[threadIdx.x] += t;
        __syncthreads();
    }
    if (i < n) g_off[i] = s[threadIdx.x] - v;
    if (threadIdx.x == 1023) g_bsum[blockIdx.x] = s[1023];
}

__global__ void k_scan2(int nb) {
    __shared__ int s[128];
    int v = (threadIdx.x < nb) ? g_bsum[threadIdx.x] : 0;
    s[threadIdx.x] = v;
    __syncthreads();
    #pragma unroll
    for (int o = 1; o < 128; o <<= 1) {
        int t = (threadIdx.x >= o) ? s[threadIdx.x - o] : 0;
        __syncthreads();
        s[threadIdx.x] += t;
        __syncthreads();
    }
    if (threadIdx.x < nb) g_bsum[threadIdx.x] = s[threadIdx.x] - v;
}

__global__ void k_scan3(int n, int e) {
    int i = blockIdx.x * blockDim.x + threadIdx.x;
    if (i < n) {
        int o = g_off[i] + g_bsum[i >> 10];
        g_off[i] = o;
        g_cur[i] = o;
        g_deg[i] = rsqrtf(g_deg[i]);
    }
    if (i == 0) g_off[n] = e;
}

__global__ void k_build(const int* __restrict__ row, const int* __restrict__ col,
                        const float* __restrict__ ew, int e) {
    int i = blockIdx.x * blockDim.x + threadIdx.x;
    if (i < e) {
        int r = row[i], c = col[i];
        int p = atomicAdd(&g_cur[c], 1);
        float w = g_deg[r] * ew[i] * g_deg[c];
        g_epack[p] = make_int2(r, __float_as_int(w));
    }
}

// ---------------- A2 / A1 tf32 pre-rounding ----------------
__global__ void k_tr(const float* __restrict__ A2, const float* __restrict__ A1) {
    int i = blockIdx.x * blockDim.x + threadIdx.x;
    if (i < 64 * 384) g_A2t[i] = to_tf32(A2[i]);
    else if (i < 64 * 384 + 64 * 64) {
        int j = i - 64 * 384;
        g_A1t[j] = to_tf32(A1[j]);
    }
}

// ---------------- aggregation: warp per target node, atomic-free ------------
__global__ void k_agg(const float* __restrict__ hin, float* __restrict__ hout, int n) {
    int warp = (blockIdx.x * blockDim.x + threadIdx.x) >> 5;
    int lane = threadIdx.x & 31;
    if (warp >= n) return;
    float d = g_deg[warp];
    float sl = d * d;
    const float2* base = (const float2*)hin + lane;
    float2 v = base[(size_t)warp * 32];
    float ax = v.x * sl, ay = v.y * sl;
    int j = g_off[warp], jend = g_off[warp + 1];
    for (; j + 4 <= jend; j += 4) {
        int2 p0 = __ldg(&g_epack[j]);
        int2 p1 = __ldg(&g_epack[j + 1]);
        int2 p2 = __ldg(&g_epack[j + 2]);
        int2 p3 = __ldg(&g_epack[j + 3]);
        float2 h0 = base[(size_t)p0.x * 32];
        float2 h1 = base[(size_t)p1.x * 32];
        float2 h2 = base[(size_t)p2.x * 32];
        float2 h3 = base[(size_t)p3.x * 32];
        float w0 = __int_as_float(p0.y), w1 = __int_as_float(p1.y);
        float w2 = __int_as_float(p2.y), w3 = __int_as_float(p3.y);
        ax = fmaf(w0, h0.x, ax); ay = fmaf(w0, h0.y, ay);
        ax = fmaf(w1, h1.x, ax); ay = fmaf(w1, h1.y, ay);
        ax = fmaf(w2, h2.x, ax); ay = fmaf(w2, h2.y, ay);
        ax = fmaf(w3, h3.x, ax); ay = fmaf(w3, h3.y, ay);
    }
    for (; j < jend; ++j) {
        int2 p = __ldg(&g_epack[j]);
        float w = __int_as_float(p.y);
        float2 hv = base[(size_t)p.x * 32];
        ax = fmaf(w, hv.x, ax);
        ay = fmaf(w, hv.y, ay);
    }
    *((float2*)hout + lane + (size_t)warp * 32) = make_float2(ax, ay);
}

// ---------------- fp32 GEMM micro-kernel (gemm128, Ws stride 64) ------------
__device__ __forceinline__ void mm_core8(const float (*As)[65], const float (*Ws)[64],
                                         int r0, int c0, u64 acc[8][4]) {
    #pragma unroll 4
    for (int k = 0; k < 64; k++) {
        const u64* wr = (const u64*)&Ws[k][c0];
        u64 w0 = wr[0], w1 = wr[1], w2 = wr[2], w3 = wr[3];
        #pragma unroll
        for (int i = 0; i < 8; i++) {
            u64 ap = pack2(As[r0 + i][k]);
            FMA2(acc[i][0], ap, w0);
            FMA2(acc[i][1], ap, w1);
            FMA2(acc[i][2], ap, w2);
            FMA2(acc[i][3], ap, w3);
        }
    }
}

__device__ __forceinline__ void load_A_tile(float (*As)[65], const float* A,
                                            int row0, int nrows, int tid, int nthr) {
    for (int i = tid; i < 128 * 16; i += nthr) {
        int r = i >> 4, c4 = (i & 15) << 2;
        float4 v = make_float4(0.f, 0.f, 0.f, 0.f);
        int gr = row0 + r;
        if (gr < nrows) v = *(const float4*)(A + (size_t)gr * 64 + c4);
        As[r][c4] = v.x; As[r][c4 + 1] = v.y; As[r][c4 + 2] = v.z; As[r][c4 + 3] = v.w;
    }
}
__device__ __forceinline__ void load_W_tile64(float (*Ws)[64], const float* W,
                                              int tid, int nthr) {
    for (int i = tid; i < 64 * 16; i += nthr) {
        int r = i >> 4, c4 = (i & 15) << 2;
        *(float4*)(&Ws[r][c4]) = *(const float4*)(W + (size_t)r * 64 + c4);
    }
}

#define SM_BYTES ((128 * 65 + 64 * 64) * 4)

// ---------------- GEMM: C = relu(A[N,64] @ W[64,64]) (layer 1) --------------
__global__ __launch_bounds__(128) void gemm128(const float* __restrict__ A,
                                               const float* __restrict__ W,
                                               float* __restrict__ C, int nrows) {
    extern __shared__ float sm[];
    float (*As)[65] = (float(*)[65])sm;
    float (*Ws)[64] = (float(*)[64])(sm + 128 * 65);
    int tid = threadIdx.x;
    int row0 = blockIdx.x * 128;

    load_A_tile(As, A, row0, nrows, tid, 128);
    load_W_tile64(Ws, W, tid, 128);
    __syncthreads();

    int r0 = (tid >> 3) * 8, c0 = (tid & 7) * 8;
    u64 acc[8][4] = {};
    mm_core8(As, Ws, r0, c0, acc);

    #pragma unroll
    for (int i = 0; i < 8; i++) {
        int gr = row0 + r0 + i;
        if (gr < nrows) {
            float o[8];
            #pragma unroll
            for (int jp = 0; jp < 4; jp++) unpack2(acc[i][jp], o[2 * jp], o[2 * jp + 1]);
            #pragma unroll
            for (int j = 0; j < 8; j++) o[j] = fmaxf(o[j], 0.f);
            float* cp = C + (size_t)gr * 64 + c0;
            *(float4*)(cp)     = make_float4(o[0], o[1], o[2], o[3]);
            *(float4*)(cp + 4) = make_float4(o[4], o[5], o[6], o[7]);
        }
    }
}

// ---------------- fused readout: h = relu(Z@W2) (exact fp32, FFMA2)
//                  T = relu(h@A1+b1)   (tf32 MMA, smem only)
//                  r = T@A2 + b2       (tf32 MMA)
// 256 threads, 128 rows per block. Hs stride 65 (stage0 conflict-free),
// Ws stride 68 (b-fragment LDS conflict-free: bank = 4*tg + g).
#define RA_WSTR 68
#define RA_SMEM ((128 * 65 + 64 * RA_WSTR) * 4)

__global__ __launch_bounds__(256) void readout_all(
        const float* __restrict__ Z, const float* __restrict__ W2,
        const float* __restrict__ b1, const float* __restrict__ b2,
        float* __restrict__ h_out, float* __restrict__ r_out, int nrows) {
    extern __shared__ float sm[];
    float (*Hs)[65]      = (float(*)[65])sm;                 // Z -> h -> T
    float (*Ws)[RA_WSTR] = (float(*)[RA_WSTR])(sm + 128 * 65);
    int tid = threadIdx.x, wid = tid >> 5, lane = tid & 31;
    int row0 = blockIdx.x * 128;

    load_A_tile(Hs, Z, row0, nrows, tid, 256);
    for (int i = tid; i < 64 * 16; i += 256) {
        int r = i >> 4, c4 = (i & 15) << 2;
        *(float4*)(&Ws[r][c4]) = *(const float4*)(W2 + (size_t)r * 64 + c4);
    }
    __syncthreads();

    // ---- stage 0: h = relu(Z @ W2), exact fp32 via FFMA2 (4 rows x 8 cols) --
    {
        int r0 = (tid >> 3) * 4, c0 = (tid & 7) * 8;
        u64 acc[4][4] = {};
        #pragma unroll 4
        for (int k = 0; k < 64; k++) {
            const u64* wr = (const u64*)&Ws[k][c0];
            u64 w0 = wr[0], w1 = wr[1], w2 = wr[2], w3 = wr[3];
            #pragma unroll
            for (int i = 0; i < 4; i++) {
                u64 ap = pack2(Hs[r0 + i][k]);
                FMA2(acc[i][0], ap, w0);
                FMA2(acc[i][1], ap, w1);
                FMA2(acc[i][2], ap, w2);
                FMA2(acc[i][3], ap, w3);
            }
        }
        __syncthreads();                // all Hs(Z) reads done before overwrite
        #pragma unroll
        for (int i = 0; i < 4; i++) {
            float o[8];
            #pragma unroll
            for (int jp = 0; jp < 4; jp++) unpack2(acc[i][jp], o[2 * jp], o[2 * jp + 1]);
            #pragma unroll
            for (int j = 0; j < 8; j++) o[j] = fmaxf(o[j], 0.f);
            #pragma unroll
            for (int j = 0; j < 8; j++) Hs[r0 + i][c0 + j] = o[j];
            int gr = row0 + r0 + i;
            if (gr < nrows) {
                float* cp = h_out + (size_t)gr * 64 + c0;
                *(float4*)(cp)     = make_float4(o[0], o[1], o[2], o[3]);
                *(float4*)(cp + 4) = make_float4(o[4], o[5], o[6], o[7]);
            }
        }
        // load A1 (pre-tf32) into Ws
        for (int i = tid; i < 64 * 16; i += 256) {
            int r = i >> 4, c4 = (i & 15) << 2;
            *(float4*)(&Ws[r][c4]) = *(const float4*)(g_A1t + r * 64 + c4);
        }
        __syncthreads();
    }

    int g = lane >> 2, tg = lane & 3;
    int m0 = wid * 16;

    // ---- stage 1: T = relu(h @ A1 + b1) via tf32 MMA, T -> Hs (tf32-rounded)
    {
        float acc[8][4];
        #pragma unroll
        for (int nt = 0; nt < 8; nt++)
            #pragma unroll
            for (int q = 0; q < 4; q++) acc[nt][q] = 0.f;

        #pragma unroll
        for (int kc = 0; kc < 8; kc++) {
            int k0 = kc * 8;
            unsigned a[4];
            a[0] = to_tf32_u(Hs[m0 + g][k0 + tg]);
            a[1] = to_tf32_u(Hs[m0 + g + 8][k0 + tg]);
            a[2] = to_tf32_u(Hs[m0 + g][k0 + tg + 4]);
            a[3] = to_tf32_u(Hs[m0 + g + 8][k0 + tg + 4]);
            #pragma unroll
            for (int nt = 0; nt < 8; nt++) {
                unsigned b[2];
                b[0] = __float_as_uint(Ws[k0 + tg][nt * 8 + g]);
                b[1] = __float_as_uint(Ws[k0 + tg + 4][nt * 8 + g]);
                mma_tf32(acc[nt], a, b);
            }
        }
        // rows m0..m0+15 are warp-private: all reads above precede these writes
        // in program order, so no block sync needed before the overwrite.
        #pragma unroll
        for (int nt = 0; nt < 8; nt++) {
            int c = nt * 8 + 2 * tg;
            float bx = b1[c], by = b1[c + 1];
            Hs[m0 + g][c]         = to_tf32(fmaxf(acc[nt][0] + bx, 0.f));
            Hs[m0 + g][c + 1]     = to_tf32(fmaxf(acc[nt][1] + by, 0.f));
            Hs[m0 + g + 8][c]     = to_tf32(fmaxf(acc[nt][2] + bx, 0.f));
            Hs[m0 + g + 8][c + 1] = to_tf32(fmaxf(acc[nt][3] + by, 0.f));
        }
    }

    // ---- stage 2: r = T @ A2 + b2, 6 column tiles of A2 ----
    int gr0 = row0 + m0 + g;
    int gr1 = gr0 + 8;
    for (int ct = 0; ct < 6; ct++) {
        __syncthreads();                       // prior Ws reads complete
        for (int i = tid; i < 64 * 16; i += 256) {
            int r = i >> 4, c4 = (i & 15) << 2;
            *(float4*)(&Ws[r][c4]) = *(const float4*)(g_A2t + r * 384 + ct * 64 + c4);
        }
        __syncthreads();

        float acc[8][4];
        #pragma unroll
        for (int nt = 0; nt < 8; nt++)
            #pragma unroll
            for (int q = 0; q < 4; q++) acc[nt][q] = 0.f;

        #pragma unroll
        for (int kc = 0; kc < 8; kc++) {
            int k0 = kc * 8;
            unsigned a[4];
            a[0] = __float_as_uint(Hs[m0 + g][k0 + tg]);
            a[1] = __float_as_uint(Hs[m0 + g + 8][k0 + tg]);
            a[2] = __float_as_uint(Hs[m0 + g][k0 + tg + 4]);
            a[3] = __float_as_uint(Hs[m0 + g + 8][k0 + tg + 4]);
            #pragma unroll
            for (int nt = 0; nt < 8; nt++) {
                unsigned b[2];
                b[0] = __float_as_uint(Ws[k0 + tg][nt * 8 + g]);
                b[1] = __float_as_uint(Ws[k0 + tg + 4][nt * 8 + g]);
                mma_tf32(acc[nt], a, b);
            }
        }

        #pragma unroll
        for (int nt = 0; nt < 8; nt++) {
            int gc = ct * 64 + nt * 8 + 2 * tg;
            float bx = b2[gc], by = b2[gc + 1];
            if (gr0 < nrows)
                *(float2*)(r_out + (size_t)gr0 * 384 + gc) =
                    make_float2(acc[nt][0] + bx, acc[nt][1] + by);
            if (gr1 < nrows)
                *(float2*)(r_out + (size_t)gr1 * 384 + gc) =
                    make_float2(acc[nt][2] + bx, acc[nt][3] + by);
        }
    }
}

// ---------------- launch ----------------
extern "C" void kernel_launch(void* const* d_in, const int* in_sizes, int n_in,
                              void* d_out, int out_size) {
    const float* x  = (const float*)d_in[0];
    const int*   ei = (const int*)d_in[1];
    const float* ew = (const float*)d_in[2];
    const float* W1 = (const float*)d_in[3];
    const float* W2 = (const float*)d_in[4];
    const float* A1 = (const float*)d_in[5];
    const float* b1 = (const float*)d_in[6];
    const float* A2 = (const float*)d_in[7];
    const float* b2 = (const float*)d_in[8];

    int n = in_sizes[0] / 64;       // 100000
    int e = in_sizes[2];            // 1600000
    const int* row = ei;
    const int* col = ei + e;

    float* out   = (float*)d_out;
    float* r_out = out;                       // [n, 384]
    float* h_out = out + (size_t)n * 384;     // [n, 64]

    float *bufA, *bufB;
    cudaGetSymbolAddress((void**)&bufA, g_bufA);
    cudaGetSymbolAddress((void**)&bufB, g_bufB);

    static int smem_set = 0;
    if (!smem_set) {
        cudaFuncSetAttribute(gemm128, cudaFuncAttributeMaxDynamicSharedMemorySize, SM_BYTES);
        cudaFuncSetAttribute(readout_all, cudaFuncAttributeMaxDynamicSharedMemorySize, RA_SMEM);
        smem_set = 1;
    }

    int gn = (n + 255) / 256;
    int ge = (e + 255) / 256;
    int nb = (n + 1023) / 1024;
    int mt = (n + 127) / 128;
    int gagg = (n * 32 + 255) / 256;

    // CSR-by-target build (shared by both GCN layers)
    k_init<<<gn, 256>>>(n);
    k_count<<<ge, 256>>>(col, ew, e);
    k_scan1<<<nb, 1024>>>(n);
    k_scan2<<<1, 128>>>(nb);
    k_scan3<<<gn, 256>>>(n, e);
    k_build<<<ge, 256>>>(row, col, ew, e);
    k_tr<<<(64 * 384 + 64 * 64 + 255) / 256, 256>>>(A2, A1);

    // Layer 1 (reassociated): Y = S·x ; h1 = relu(Y @ W1)
    k_agg<<<gagg, 256>>>(x, bufA, n);
    gemm128<<<mt, 128, SM_BYTES>>>(bufA, W1, bufB, n);

    // Layer 2 + full readout fused:
    // Z = S·h1 ; h = relu(Z@W2) ; r = relu(h@A1+b1)@A2 + b2
    k_agg<<<gagg, 256>>>(bufB, bufA, n);
    readout_all<<<mt, 256, RA_SMEM>>>(bufA, W2, b1, b2, h_out, r_out, n);
}

// round 14
// speedup vs baseline: 1.1737x; 1.1737x over previous
#include <cuda_runtime.h>
#include <cstdint>

#define NMAX 100000
#define EMAX 1600000
#define H 64

typedef unsigned long long u64;

// ---------------- device scratch (no allocations allowed) ----------------
__device__ float g_bufA[NMAX * H];
__device__ float g_bufB[NMAX * H];
__device__ float g_W1t[64 * 64];   // W1 tf32-rounded [k][n]
__device__ float g_W2t[64 * 64];   // W2 tf32-rounded [k][n]
__device__ float g_A1t[64 * 64];   // A1 tf32-rounded [k][n]
__device__ float g_A2t[64 * 384];  // A2 tf32-rounded [k][n]
__device__ float g_deg[NMAX];      // degree, then dinv = rsqrt(deg)
__device__ int   g_cnt[NMAX];      // in-degree (edge count) histogram
__device__ int   g_off[NMAX + 1];  // CSR offsets by target node
__device__ int   g_cur[NMAX];      // scatter cursors
__device__ int2  g_epack[EMAX];    // (src_row, bitcast(norm)) grouped by target
__device__ int   g_bsum[128];      // scan block sums

__device__ __forceinline__ float to_tf32(float x) {
    unsigned int u;
    asm("cvt.rna.tf32.f32 %0, %1;" : "=r"(u) : "f"(x));
    return __uint_as_float(u);
}
__device__ __forceinline__ unsigned to_tf32_u(float x) {
    unsigned int u;
    asm("cvt.rna.tf32.f32 %0, %1;" : "=r"(u) : "f"(x));
    return u;
}

// warp-level tf32 MMA (sm_80+ baseline feature, valid for compute_103)
__device__ __forceinline__ void mma_tf32(float c[4], const unsigned a[4],
                                         const unsigned b[2]) {
    asm volatile(
        "mma.sync.aligned.m16n8k8.row.col.f32.tf32.tf32.f32 "
        "{%0,%1,%2,%3}, {%4,%5,%6,%7}, {%8,%9}, {%0,%1,%2,%3};"
        : "+f"(c[0]), "+f"(c[1]), "+f"(c[2]), "+f"(c[3])
        : "r"(a[0]), "r"(a[1]), "r"(a[2]), "r"(a[3]), "r"(b[0]), "r"(b[1]));
}

// ---------------- init + weight tf32 pre-rounding (fused) ----------------
__global__ void k_init(int n, const float* __restrict__ W1,
                       const float* __restrict__ W2,
                       const float* __restrict__ A1,
                       const float* __restrict__ A2) {
    int i = blockIdx.x * blockDim.x + threadIdx.x;
    if (i < n) { g_deg[i] = 1.0f; g_cnt[i] = 0; }   // self-loop weight 1
    if (i < 64 * 64) {
        g_W1t[i] = to_tf32(W1[i]);
        g_W2t[i] = to_tf32(W2[i]);
        g_A1t[i] = to_tf32(A1[i]);
    }
    if (i < 64 * 384) g_A2t[i] = to_tf32(A2[i]);
}

__global__ void k_count(const int* __restrict__ col, const float* __restrict__ ew, int e) {
    int i = blockIdx.x * blockDim.x + threadIdx.x;
    if (i < e) {
        int c = col[i];
        atomicAdd(&g_deg[c], ew[i]);
        atomicAdd(&g_cnt[c], 1);
    }
}

__global__ void k_scan1(int n) {
    __shared__ int s[1024];
    int i = blockIdx.x * 1024 + threadIdx.x;
    int v = (i < n) ? g_cnt[i] : 0;
    s[threadIdx.x] = v;
    __syncthreads();
    #pragma unroll
    for (int o = 1; o < 1024; o <<= 1) {
        int t = (threadIdx.x >= o) ? s[threadIdx.x - o] : 0;
        __syncthreads();
        s[threadIdx.x] += t;
        __syncthreads();
    }
    if (i < n) g_off[i] = s[threadIdx.x] - v;
    if (threadIdx.x == 1023) g_bsum[blockIdx.x] = s[1023];
}

__global__ void k_scan2(int nb) {
    __shared__ int s[128];
    int v = (threadIdx.x < nb) ? g_bsum[threadIdx.x] : 0;
    s[threadIdx.x] = v;
    __syncthreads();
    #pragma unroll
    for (int o = 1; o < 128; o <<= 1) {
        int t = (threadIdx.x >= o) ? s[threadIdx.x - o] : 0;
        __syncthreads();
        s[threadIdx.x] += t;
        __syncthreads();
    }
    if (threadIdx.x < nb) g_bsum[threadIdx.x] = s[threadIdx.x] - v;
}

__global__ void k_scan3(int n, int e) {
    int i = blockIdx.x * blockDim.x + threadIdx.x;
    if (i < n) {
        int o = g_off[i] + g_bsum[i >> 10];
        g_off[i] = o;
        g_cur[i] = o;
        g_deg[i] = rsqrtf(g_deg[i]);
    }
    if (i == 0) g_off[n] = e;
}

__global__ void k_build(const int* __restrict__ row, const int* __restrict__ col,
                        const float* __restrict__ ew, int e) {
    int i = blockIdx.x * blockDim.x + threadIdx.x;
    if (i < e) {
        int r = row[i], c = col[i];
        int p = atomicAdd(&g_cur[c], 1);
        float w = g_deg[r] * ew[i] * g_deg[c];
        g_epack[p] = make_int2(r, __float_as_int(w));
    }
}

// ---------------- aggregation: warp per target node, atomic-free ------------
__global__ void k_agg(const float* __restrict__ hin, float* __restrict__ hout, int n) {
    int warp = (blockIdx.x * blockDim.x + threadIdx.x) >> 5;
    int lane = threadIdx.x & 31;
    if (warp >= n) return;
    float d = g_deg[warp];
    float sl = d * d;
    const float2* base = (const float2*)hin + lane;
    float2 v = base[(size_t)warp * 32];
    float ax = v.x * sl, ay = v.y * sl;
    int j = g_off[warp], jend = g_off[warp + 1];
    for (; j + 4 <= jend; j += 4) {
        int2 p0 = __ldg(&g_epack[j]);
        int2 p1 = __ldg(&g_epack[j + 1]);
        int2 p2 = __ldg(&g_epack[j + 2]);
        int2 p3 = __ldg(&g_epack[j + 3]);
        float2 h0 = base[(size_t)p0.x * 32];
        float2 h1 = base[(size_t)p1.x * 32];
        float2 h2 = base[(size_t)p2.x * 32];
        float2 h3 = base[(size_t)p3.x * 32];
        float w0 = __int_as_float(p0.y), w1 = __int_as_float(p1.y);
        float w2 = __int_as_float(p2.y), w3 = __int_as_float(p3.y);
        ax = fmaf(w0, h0.x, ax); ay = fmaf(w0, h0.y, ay);
        ax = fmaf(w1, h1.x, ax); ay = fmaf(w1, h1.y, ay);
        ax = fmaf(w2, h2.x, ax); ay = fmaf(w2, h2.y, ay);
        ax = fmaf(w3, h3.x, ax); ay = fmaf(w3, h3.y, ay);
    }
    for (; j < jend; ++j) {
        int2 p = __ldg(&g_epack[j]);
        float w = __int_as_float(p.y);
        float2 hv = base[(size_t)p.x * 32];
        ax = fmaf(w, hv.x, ax);
        ay = fmaf(w, hv.y, ay);
    }
    *((float2*)hout + lane + (size_t)warp * 32) = make_float2(ax, ay);
}

// ---------------- shared smem geometry for MMA kernels ----------------
#define HS_STR 72
#define WS_STR 68
#define MM_SMEM ((128 * HS_STR + 64 * WS_STR) * 4)

__device__ __forceinline__ void load_rows128(float (*Hs)[HS_STR], const float* A,
                                             int row0, int nrows, int tid) {
    for (int i = tid; i < 128 * 16; i += 256) {
        int r = i >> 4, c4 = (i & 15) << 2;
        float4 v = make_float4(0.f, 0.f, 0.f, 0.f);
        int gr = row0 + r;
        if (gr < nrows) v = *(const float4*)(A + (size_t)gr * 64 + c4);
        *(float4*)(&Hs[r][c4]) = v;
    }
}
__device__ __forceinline__ void load_w64(float (*Ws)[WS_STR], const float* W,
                                         int ldw, int col0, int tid) {
    for (int i = tid; i < 64 * 16; i += 256) {
        int r = i >> 4, c4 = (i & 15) << 2;
        *(float4*)(&Ws[r][c4]) = *(const float4*)(W + (size_t)r * ldw + col0 + c4);
    }
}

// 64-col MMA sweep: acc[nt][q] += tf32(Hs rows m0..m0+15) @ Ws[:, nt*8..]
// ROUND_A: cvt.rna a-fragments (Hs holds raw fp32) vs bit-exact reinterpret.
template <int ROUND_A>
__device__ __forceinline__ void mma_sweep(const float (*Hs)[HS_STR],
                                          const float (*Ws)[WS_STR],
                                          int m0, int g, int tg, float acc[8][4]) {
    #pragma unroll
    for (int kc = 0; kc < 8; kc++) {
        int k0 = kc * 8;
        unsigned a[4];
        if (ROUND_A) {
            a[0] = to_tf32_u(Hs[m0 + g][k0 + tg]);
            a[1] = to_tf32_u(Hs[m0 + g + 8][k0 + tg]);
            a[2] = to_tf32_u(Hs[m0 + g][k0 + tg + 4]);
            a[3] = to_tf32_u(Hs[m0 + g + 8][k0 + tg + 4]);
        } else {
            a[0] = __float_as_uint(Hs[m0 + g][k0 + tg]);
            a[1] = __float_as_uint(Hs[m0 + g + 8][k0 + tg]);
            a[2] = __float_as_uint(Hs[m0 + g][k0 + tg + 4]);
            a[3] = __float_as_uint(Hs[m0 + g + 8][k0 + tg + 4]);
        }
        #pragma unroll
        for (int nt = 0; nt < 8; nt++) {
            unsigned b[2];
            b[0] = __float_as_uint(Ws[k0 + tg][nt * 8 + g]);
            b[1] = __float_as_uint(Ws[k0 + tg + 4][nt * 8 + g]);
            mma_tf32(acc[nt], a, b);
        }
    }
}

// ---------------- layer-1 GEMM: C = relu(A @ W1t), tf32 MMA -----------------
__global__ __launch_bounds__(256) void gemm_mma_relu(const float* __restrict__ A,
                                                     float* __restrict__ C, int nrows) {
    extern __shared__ float sm[];
    float (*Hs)[HS_STR] = (float(*)[HS_STR])sm;
    float (*Ws)[WS_STR] = (float(*)[WS_STR])(sm + 128 * HS_STR);
    int tid = threadIdx.x, wid = tid >> 5, lane = tid & 31;
    int row0 = blockIdx.x * 128;

    load_rows128(Hs, A, row0, nrows, tid);
    load_w64(Ws, g_W1t, 64, 0, tid);
    __syncthreads();

    int g = lane >> 2, tg = lane & 3;
    int m0 = wid * 16;
    float acc[8][4] = {};
    mma_sweep<1>(Hs, Ws, m0, g, tg, acc);

    int gr0 = row0 + m0 + g, gr1 = gr0 + 8;
    #pragma unroll
    for (int nt = 0; nt < 8; nt++) {
        int gc = nt * 8 + 2 * tg;
        if (gr0 < nrows)
            *(float2*)(C + (size_t)gr0 * 64 + gc) =
                make_float2(fmaxf(acc[nt][0], 0.f), fmaxf(acc[nt][1], 0.f));
        if (gr1 < nrows)
            *(float2*)(C + (size_t)gr1 * 64 + gc) =
                make_float2(fmaxf(acc[nt][2], 0.f), fmaxf(acc[nt][3], 0.f));
    }
}

// ---------------- fused all-MMA readout ----------------
// stage0: h = relu(Z @ W2)          -> h_out (fp32 accum) + Hs
// stage1: T = relu(h @ A1 + b1)     -> Hs (tf32-rounded, warp-private rows)
// stage2: r = T @ A2 + b2           -> r_out  (6 column tiles)
__global__ __launch_bounds__(256) void readout_mma(
        const float* __restrict__ Z,
        const float* __restrict__ b1, const float* __restrict__ b2,
        float* __restrict__ h_out, float* __restrict__ r_out, int nrows) {
    extern __shared__ float sm[];
    float (*Hs)[HS_STR] = (float(*)[HS_STR])sm;            // Z -> h -> T
    float (*Ws)[WS_STR] = (float(*)[WS_STR])(sm + 128 * HS_STR);
    int tid = threadIdx.x, wid = tid >> 5, lane = tid & 31;
    int row0 = blockIdx.x * 128;
    int g = lane >> 2, tg = lane & 3;
    int m0 = wid * 16;
    int gr0 = row0 + m0 + g, gr1 = gr0 + 8;

    load_rows128(Hs, Z, row0, nrows, tid);
    load_w64(Ws, g_W2t, 64, 0, tid);
    __syncthreads();

    // ---- stage 0: h = relu(Z @ W2) ----
    {
        float acc[8][4] = {};
        mma_sweep<1>(Hs, Ws, m0, g, tg, acc);
        // rows m0..m0+15 are warp-private: all a-frag reads above precede
        // these writes in this warp's program order; no other warp touches them.
        #pragma unroll
        for (int nt = 0; nt < 8; nt++) {
            int c = nt * 8 + 2 * tg;
            float o0 = fmaxf(acc[nt][0], 0.f), o1 = fmaxf(acc[nt][1], 0.f);
            float o2 = fmaxf(acc[nt][2], 0.f), o3 = fmaxf(acc[nt][3], 0.f);
            Hs[m0 + g][c]         = o0;
            Hs[m0 + g][c + 1]     = o1;
            Hs[m0 + g + 8][c]     = o2;
            Hs[m0 + g + 8][c + 1] = o3;
            if (gr0 < nrows) *(float2*)(h_out + (size_t)gr0 * 64 + c) = make_float2(o0, o1);
            if (gr1 < nrows) *(float2*)(h_out + (size_t)gr1 * 64 + c) = make_float2(o2, o3);
        }
    }

    // swap Ws -> A1 (block-wide resource: sync around reload)
    __syncthreads();
    load_w64(Ws, g_A1t, 64, 0, tid);
    __syncthreads();

    // ---- stage 1: T = relu(h @ A1 + b1), tf32-rounded into Hs ----
    {
        float acc[8][4] = {};
        mma_sweep<1>(Hs, Ws, m0, g, tg, acc);
        #pragma unroll
        for (int nt = 0; nt < 8; nt++) {
            int c = nt * 8 + 2 * tg;
            float bx = b1[c], by = b1[c + 1];
            Hs[m0 + g][c]         = to_tf32(fmaxf(acc[nt][0] + bx, 0.f));
            Hs[m0 + g][c + 1]     = to_tf32(fmaxf(acc[nt][1] + by, 0.f));
            Hs[m0 + g + 8][c]     = to_tf32(fmaxf(acc[nt][2] + bx, 0.f));
            Hs[m0 + g + 8][c + 1] = to_tf32(fmaxf(acc[nt][3] + by, 0.f));
        }
    }

    // ---- stage 2: r = T @ A2 + b2, 6 column tiles ----
    for (int ct = 0; ct < 6; ct++) {
        __syncthreads();                       // prior Ws reads complete
        load_w64(Ws, g_A2t, 384, ct * 64, tid);
        __syncthreads();

        float acc[8][4] = {};
        mma_sweep<0>(Hs, Ws, m0, g, tg, acc);

        #pragma unroll
        for (int nt = 0; nt < 8; nt++) {
            int gc = ct * 64 + nt * 8 + 2 * tg;
            float bx = b2[gc], by = b2[gc + 1];
            if (gr0 < nrows)
                *(float2*)(r_out + (size_t)gr0 * 384 + gc) =
                    make_float2(acc[nt][0] + bx, acc[nt][1] + by);
            if (gr1 < nrows)
                *(float2*)(r_out + (size_t)gr1 * 384 + gc) =
                    make_float2(acc[nt][2] + bx, acc[nt][3] + by);
        }
    }
}

// ---------------- launch ----------------
extern "C" void kernel_launch(void* const* d_in, const int* in_sizes, int n_in,
                              void* d_out, int out_size) {
    const float* x  = (const float*)d_in[0];
    const int*   ei = (const int*)d_in[1];
    const float* ew = (const float*)d_in[2];
    const float* W1 = (const float*)d_in[3];
    const float* W2 = (const float*)d_in[4];
    const float* A1 = (const float*)d_in[5];
    const float* b1 = (const float*)d_in[6];
    const float* A2 = (const float*)d_in[7];
    const float* b2 = (const float*)d_in[8];

    int n = in_sizes[0] / 64;       // 100000
    int e = in_sizes[2];            // 1600000
    const int* row = ei;
    const int* col = ei + e;

    float* out   = (float*)d_out;
    float* r_out = out;                       // [n, 384]
    float* h_out = out + (size_t)n * 384;     // [n, 64]

    float *bufA, *bufB;
    cudaGetSymbolAddress((void**)&bufA, g_bufA);
    cudaGetSymbolAddress((void**)&bufB, g_bufB);

    static int smem_set = 0;
    if (!smem_set) {
        cudaFuncSetAttribute(gemm_mma_relu, cudaFuncAttributeMaxDynamicSharedMemorySize, MM_SMEM);
        cudaFuncSetAttribute(readout_mma, cudaFuncAttributeMaxDynamicSharedMemorySize, MM_SMEM);
        smem_set = 1;
    }

    int gn = (n + 255) / 256;
    int ge = (e + 255) / 256;
    int nb = (n + 1023) / 1024;
    int mt = (n + 127) / 128;
    int gagg = (n * 32 + 255) / 256;

    // CSR-by-target build (shared by both GCN layers) + weight pre-rounding
    k_init<<<gn, 256>>>(n, W1, W2, A1, A2);
    k_count<<<ge, 256>>>(col, ew, e);
    k_scan1<<<nb, 1024>>>(n);
    k_scan2<<<1, 128>>>(nb);
    k_scan3<<<gn, 256>>>(n, e);
    k_build<<<ge, 256>>>(row, col, ew, e);

    // Layer 1 (reassociated): Y = S·x ; h1 = relu(Y @ W1)  [tf32 MMA]
    k_agg<<<gagg, 256>>>(x, bufA, n);
    gemm_mma_relu<<<mt, 256, MM_SMEM>>>(bufA, bufB, n);

    // Layer 2 + full readout, all tf32 MMA:
    // Z = S·h1 ; h = relu(Z@W2) ; r = relu(h@A1+b1)@A2 + b2
    k_agg<<<gagg, 256>>>(bufB, bufA, n);
    readout_mma<<<mt, 256, MM_SMEM>>>(bufA, b1, b2, h_out, r_out, n);
}

// round 17
// speedup vs baseline: 1.2030x; 1.0250x over previous
#include <cuda_runtime.h>
#include <cstdint>

#define NMAX 100000
#define EMAX 1600000
#define H 64

typedef unsigned long long u64;

// ---------------- device scratch (no allocations allowed) ----------------
__device__ float g_bufA[NMAX * H];
__device__ float g_bufB[NMAX * H];
__device__ float g_W1t[64 * 64];   // W1 tf32-rounded [k][n]
__device__ float g_W2t[64 * 64];   // W2 tf32-rounded [k][n]
__device__ float g_A1t[64 * 64];   // A1 tf32-rounded [k][n]
__device__ float g_A2t[64 * 384];  // A2 tf32-rounded [k][n]
__device__ float g_deg[NMAX];      // degree, then dinv = rsqrt(deg)
__device__ int   g_cnt[NMAX];      // in-degree (edge count) histogram
__device__ int   g_off[NMAX + 1];  // CSR offsets by target node
__device__ int   g_cur[NMAX];      // scatter cursors
__device__ int2  g_epack[EMAX];    // (src_row, bitcast(norm)) grouped by target
__device__ int   g_bsum[128];      // scan1 raw tile sums

__device__ __forceinline__ float to_tf32(float x) {
    unsigned int u;
    asm("cvt.rna.tf32.f32 %0, %1;" : "=r"(u) : "f"(x));
    return __uint_as_float(u);
}
__device__ __forceinline__ unsigned to_tf32_u(float x) {
    unsigned int u;
    asm("cvt.rna.tf32.f32 %0, %1;" : "=r"(u) : "f"(x));
    return u;
}

// warp-level tf32 MMA (sm_80+ baseline feature, valid for compute_103)
__device__ __forceinline__ void mma_tf32(float c[4], const unsigned a[4],
                                         const unsigned b[2]) {
    asm volatile(
        "mma.sync.aligned.m16n8k8.row.col.f32.tf32.tf32.f32 "
        "{%0,%1,%2,%3}, {%4,%5,%6,%7}, {%8,%9}, {%0,%1,%2,%3};"
        : "+f"(c[0]), "+f"(c[1]), "+f"(c[2]), "+f"(c[3])
        : "r"(a[0]), "r"(a[1]), "r"(a[2]), "r"(a[3]), "r"(b[0]), "r"(b[1]));
}

// ---------------- init + weight tf32 pre-rounding (fused) ----------------
__global__ void k_init(int n, const float* __restrict__ W1,
                       const float* __restrict__ W2,
                       const float* __restrict__ A1,
                       const float* __restrict__ A2) {
    int i = blockIdx.x * blockDim.x + threadIdx.x;
    if (i < n) { g_deg[i] = 1.0f; g_cnt[i] = 0; }   // self-loop weight 1
    if (i < 64 * 64) {
        g_W1t[i] = to_tf32(W1[i]);
        g_W2t[i] = to_tf32(W2[i]);
        g_A1t[i] = to_tf32(A1[i]);
    }
    if (i < 64 * 384) g_A2t[i] = to_tf32(A2[i]);
}

__global__ void k_count(const int* __restrict__ col, const float* __restrict__ ew, int e) {
    int i = blockIdx.x * blockDim.x + threadIdx.x;
    if (i < e) {
        int c = col[i];
        atomicAdd(&g_deg[c], ew[i]);
        atomicAdd(&g_cnt[c], 1);
    }
}

__global__ void k_scan1(int n) {
    __shared__ int s[1024];
    int i = blockIdx.x * 1024 + threadIdx.x;
    int v = (i < n) ? g_cnt[i] : 0;
    s[threadIdx.x] = v;
    __syncthreads();
    #pragma unroll
    for (int o = 1; o < 1024; o <<= 1) {
        int t = (threadIdx.x >= o) ? s[threadIdx.x - o] : 0;
        __syncthreads();
        s[threadIdx.x] += t;
        __syncthreads();
    }
    if (i < n) g_off[i] = s[threadIdx.x] - v;              // tile-exclusive
    if (threadIdx.x == 1023) g_bsum[blockIdx.x] = s[1023]; // raw tile sum
}

// scan3 with fused bsum-prefix reduction (replaces old k_scan2+k_scan3).
// 256 threads/block => whole block lies inside one 1024-tile of scan1, so
// the needed prefix (sum of earlier tile sums) is uniform per block.
__global__ void k_scan3(int n, int e) {
    __shared__ int ss[128];
    int t = threadIdx.x;
    int tile = (blockIdx.x * 256) >> 10;
    if (t < 128) ss[t] = (t < tile) ? g_bsum[t] : 0;
    __syncthreads();
    #pragma unroll
    for (int o = 64; o > 0; o >>= 1) {
        if (t < o) ss[t] += ss[t + o];
        __syncthreads();
    }
    int pref = ss[0];
    int i = blockIdx.x * 256 + t;
    if (i < n) {
        int o = g_off[i] + pref;
        g_off[i] = o;
        g_cur[i] = o;
        g_deg[i] = rsqrtf(g_deg[i]);
    }
    if (i == 0) g_off[n] = e;
}

__global__ void k_build(const int* __restrict__ row, const int* __restrict__ col,
                        const float* __restrict__ ew, int e) {
    int i = blockIdx.x * blockDim.x + threadIdx.x;
    if (i < e) {
        int r = row[i], c = col[i];
        int p = atomicAdd(&g_cur[c], 1);
        float w = g_deg[r] * ew[i] * g_deg[c];
        g_epack[p] = make_int2(r, __float_as_int(w));
    }
}

// ---------------- aggregation: warp per target node, atomic-free ------------
__global__ void k_agg(const float* __restrict__ hin, float* __restrict__ hout, int n) {
    int warp = (blockIdx.x * blockDim.x + threadIdx.x) >> 5;
    int lane = threadIdx.x & 31;
    if (warp >= n) return;
    float d = g_deg[warp];
    float sl = d * d;
    const float2* base = (const float2*)hin + lane;
    float2 v = base[(size_t)warp * 32];
    float ax = v.x * sl, ay = v.y * sl;
    int j = g_off[warp], jend = g_off[warp + 1];
    for (; j + 4 <= jend; j += 4) {
        int2 p0 = __ldg(&g_epack[j]);
        int2 p1 = __ldg(&g_epack[j + 1]);
        int2 p2 = __ldg(&g_epack[j + 2]);
        int2 p3 = __ldg(&g_epack[j + 3]);
        float2 h0 = base[(size_t)p0.x * 32];
        float2 h1 = base[(size_t)p1.x * 32];
        float2 h2 = base[(size_t)p2.x * 32];
        float2 h3 = base[(size_t)p3.x * 32];
        float w0 = __int_as_float(p0.y), w1 = __int_as_float(p1.y);
        float w2 = __int_as_float(p2.y), w3 = __int_as_float(p3.y);
        ax = fmaf(w0, h0.x, ax); ay = fmaf(w0, h0.y, ay);
        ax = fmaf(w1, h1.x, ax); ay = fmaf(w1, h1.y, ay);
        ax = fmaf(w2, h2.x, ax); ay = fmaf(w2, h2.y, ay);
        ax = fmaf(w3, h3.x, ax); ay = fmaf(w3, h3.y, ay);
    }
    for (; j < jend; ++j) {
        int2 p = __ldg(&g_epack[j]);
        float w = __int_as_float(p.y);
        float2 hv = base[(size_t)p.x * 32];
        ax = fmaf(w, hv.x, ax);
        ay = fmaf(w, hv.y, ay);
    }
    *((float2*)hout + lane + (size_t)warp * 32) = make_float2(ax, ay);
}

// ---------------- shared smem geometry for MMA kernels ----------------
#define HS_STR 72
#define WS_STR 68
#define MM_SMEM ((128 * HS_STR + 64 * WS_STR) * 4)

__device__ __forceinline__ void load_rows128(float (*Hs)[HS_STR], const float* A,
                                             int row0, int nrows, int tid) {
    for (int i = tid; i < 128 * 16; i += 256) {
        int r = i >> 4, c4 = (i & 15) << 2;
        float4 v = make_float4(0.f, 0.f, 0.f, 0.f);
        int gr = row0 + r;
        if (gr < nrows) v = *(const float4*)(A + (size_t)gr * 64 + c4);
        *(float4*)(&Hs[r][c4]) = v;
    }
}
__device__ __forceinline__ void load_w64(float (*Ws)[WS_STR], const float* W,
                                         int ldw, int col0, int tid) {
    for (int i = tid; i < 64 * 16; i += 256) {
        int r = i >> 4, c4 = (i & 15) << 2;
        *(float4*)(&Ws[r][c4]) = *(const float4*)(W + (size_t)r * ldw + col0 + c4);
    }
}

// 64-col MMA sweep: acc[nt][q] += tf32(Hs rows m0..m0+15) @ Ws[:, nt*8..]
template <int ROUND_A>
__device__ __forceinline__ void mma_sweep(const float (*Hs)[HS_STR],
                                          const float (*Ws)[WS_STR],
                                          int m0, int g, int tg, float acc[8][4]) {
    #pragma unroll
    for (int kc = 0; kc < 8; kc++) {
        int k0 = kc * 8;
        unsigned a[4];
        if (ROUND_A) {
            a[0] = to_tf32_u(Hs[m0 + g][k0 + tg]);
            a[1] = to_tf32_u(Hs[m0 + g + 8][k0 + tg]);
            a[2] = to_tf32_u(Hs[m0 + g][k0 + tg + 4]);
            a[3] = to_tf32_u(Hs[m0 + g + 8][k0 + tg + 4]);
        } else {
            a[0] = __float_as_uint(Hs[m0 + g][k0 + tg]);
            a[1] = __float_as_uint(Hs[m0 + g + 8][k0 + tg]);
            a[2] = __float_as_uint(Hs[m0 + g][k0 + tg + 4]);
            a[3] = __float_as_uint(Hs[m0 + g + 8][k0 + tg + 4]);
        }
        #pragma unroll
        for (int nt = 0; nt < 8; nt++) {
            unsigned b[2];
            b[0] = __float_as_uint(Ws[k0 + tg][nt * 8 + g]);
            b[1] = __float_as_uint(Ws[k0 + tg + 4][nt * 8 + g]);
            mma_tf32(acc[nt], a, b);
        }
    }
}

// ---------------- layer-1 GEMM: C = relu(A @ W1t), tf32 MMA -----------------
__global__ __launch_bounds__(256) void gemm_mma_relu(const float* __restrict__ A,
                                                     float* __restrict__ C, int nrows) {
    extern __shared__ float sm[];
    float (*Hs)[HS_STR] = (float(*)[HS_STR])sm;
    float (*Ws)[WS_STR] = (float(*)[WS_STR])(sm + 128 * HS_STR);
    int tid = threadIdx.x, wid = tid >> 5, lane = tid & 31;
    int row0 = blockIdx.x * 128;

    load_rows128(Hs, A, row0, nrows, tid);
    load_w64(Ws, g_W1t, 64, 0, tid);
    __syncthreads();

    int g = lane >> 2, tg = lane & 3;
    int m0 = wid * 16;
    float acc[8][4] = {};
    mma_sweep<1>(Hs, Ws, m0, g, tg, acc);

    int gr0 = row0 + m0 + g, gr1 = gr0 + 8;
    #pragma unroll
    for (int nt = 0; nt < 8; nt++) {
        int gc = nt * 8 + 2 * tg;
        if (gr0 < nrows)
            *(float2*)(C + (size_t)gr0 * 64 + gc) =
                make_float2(fmaxf(acc[nt][0], 0.f), fmaxf(acc[nt][1], 0.f));
        if (gr1 < nrows)
            *(float2*)(C + (size_t)gr1 * 64 + gc) =
                make_float2(fmaxf(acc[nt][2], 0.f), fmaxf(acc[nt][3], 0.f));
    }
}

// ---------------- fused all-MMA readout ----------------
// stage0: h = relu(Z @ W2)          -> h_out (fp32 accum) + Hs
// stage1: T = relu(h @ A1 + b1)     -> Hs (tf32-rounded, warp-private rows)
// stage2: r = T @ A2 + b2           -> r_out  (6 column tiles)
__global__ __launch_bounds__(256) void readout_mma(
        const float* __restrict__ Z,
        const float* __restrict__ b1, const float* __restrict__ b2,
        float* __restrict__ h_out, float* __restrict__ r_out, int nrows) {
    extern __shared__ float sm[];
    float (*Hs)[HS_STR] = (float(*)[HS_STR])sm;            // Z -> h -> T
    float (*Ws)[WS_STR] = (float(*)[WS_STR])(sm + 128 * HS_STR);
    int tid = threadIdx.x, wid = tid >> 5, lane = tid & 31;
    int row0 = blockIdx.x * 128;
    int g = lane >> 2, tg = lane & 3;
    int m0 = wid * 16;
    int gr0 = row0 + m0 + g, gr1 = gr0 + 8;

    load_rows128(Hs, Z, row0, nrows, tid);
    load_w64(Ws, g_W2t, 64, 0, tid);
    __syncthreads();

    // ---- stage 0: h = relu(Z @ W2) ----
    {
        float acc[8][4] = {};
        mma_sweep<1>(Hs, Ws, m0, g, tg, acc);
        // rows m0..m0+15 are warp-private across stages.
        #pragma unroll
        for (int nt = 0; nt < 8; nt++) {
            int c = nt * 8 + 2 * tg;
            float o0 = fmaxf(acc[nt][0], 0.f), o1 = fmaxf(acc[nt][1], 0.f);
            float o2 = fmaxf(acc[nt][2], 0.f), o3 = fmaxf(acc[nt][3], 0.f);
            Hs[m0 + g][c]         = o0;
            Hs[m0 + g][c + 1]     = o1;
            Hs[m0 + g + 8][c]     = o2;
            Hs[m0 + g + 8][c + 1] = o3;
            if (gr0 < nrows) *(float2*)(h_out + (size_t)gr0 * 64 + c) = make_float2(o0, o1);
            if (gr1 < nrows) *(float2*)(h_out + (size_t)gr1 * 64 + c) = make_float2(o2, o3);
        }
    }

    __syncthreads();
    load_w64(Ws, g_A1t, 64, 0, tid);
    __syncthreads();

    // ---- stage 1: T = relu(h @ A1 + b1), tf32-rounded into Hs ----
    {
        float acc[8][4] = {};
        mma_sweep<1>(Hs, Ws, m0, g, tg, acc);
        #pragma unroll
        for (int nt = 0; nt < 8; nt++) {
            int c = nt * 8 + 2 * tg;
            float bx = b1[c], by = b1[c + 1];
            Hs[m0 + g][c]         = to_tf32(fmaxf(acc[nt][0] + bx, 0.f));
            Hs[m0 + g][c + 1]     = to_tf32(fmaxf(acc[nt][1] + by, 0.f));
            Hs[m0 + g + 8][c]     = to_tf32(fmaxf(acc[nt][2] + bx, 0.f));
            Hs[m0 + g + 8][c + 1] = to_tf32(fmaxf(acc[nt][3] + by, 0.f));
        }
    }

    // ---- stage 2: r = T @ A2 + b2, 6 column tiles ----
    for (int ct = 0; ct < 6; ct++) {
        __syncthreads();
        load_w64(Ws, g_A2t, 384, ct * 64, tid);
        __syncthreads();

        float acc[8][4] = {};
        mma_sweep<0>(Hs, Ws, m0, g, tg, acc);

        #pragma unroll
        for (int nt = 0; nt < 8; nt++) {
            int gc = ct * 64 + nt * 8 + 2 * tg;
            float bx = b2[gc], by = b2[gc + 1];
            if (gr0 < nrows)
                *(float2*)(r_out + (size_t)gr0 * 384 + gc) =
                    make_float2(acc[nt][0] + bx, acc[nt][1] + by);
            if (gr1 < nrows)
                *(float2*)(r_out + (size_t)gr1 * 384 + gc) =
                    make_float2(acc[nt][2] + bx, acc[nt][3] + by);
        }
    }
}

// ---------------- launch ----------------
extern "C" void kernel_launch(void* const* d_in, const int* in_sizes, int n_in,
                              void* d_out, int out_size) {
    const float* x  = (const float*)d_in[0];
    const int*   ei = (const int*)d_in[1];
    const float* ew = (const float*)d_in[2];
    const float* W1 = (const float*)d_in[3];
    const float* W2 = (const float*)d_in[4];
    const float* A1 = (const float*)d_in[5];
    const float* b1 = (const float*)d_in[6];
    const float* A2 = (const float*)d_in[7];
    const float* b2 = (const float*)d_in[8];

    int n = in_sizes[0] / 64;       // 100000
    int e = in_sizes[2];            // 1600000
    const int* row = ei;
    const int* col = ei + e;

    float* out   = (float*)d_out;
    float* r_out = out;                       // [n, 384]
    float* h_out = out + (size_t)n * 384;     // [n, 64]

    float *bufA, *bufB;
    cudaGetSymbolAddress((void**)&bufA, g_bufA);
    cudaGetSymbolAddress((void**)&bufB, g_bufB);

    static int smem_set = 0;
    if (!smem_set) {
        cudaFuncSetAttribute(gemm_mma_relu, cudaFuncAttributeMaxDynamicSharedMemorySize, MM_SMEM);
        cudaFuncSetAttribute(readout_mma, cudaFuncAttributeMaxDynamicSharedMemorySize, MM_SMEM);
        smem_set = 1;
    }

    int gn = (n + 255) / 256;
    int ge = (e + 255) / 256;
    int nb = (n + 1023) / 1024;
    int mt = (n + 127) / 128;
    int gagg = (n * 32 + 255) / 256;

    // CSR-by-target build (shared by both GCN layers) + weight pre-rounding
    k_init<<<gn, 256>>>(n, W1, W2, A1, A2);
    k_count<<<ge, 256>>>(col, ew, e);
    k_scan1<<<nb, 1024>>>(n);
    k_scan3<<<gn, 256>>>(n, e);          // fused bsum-prefix + dinv + cursors
    k_build<<<ge, 256>>>(row, col, ew, e);

    // Layer 1 (reassociated): Y = S·x ; h1 = relu(Y @ W1)  [tf32 MMA]
    k_agg<<<gagg, 256>>>(x, bufA, n);
    gemm_mma_relu<<<mt, 256, MM_SMEM>>>(bufA, bufB, n);

    // Layer 2 + full readout, all tf32 MMA:
    // Z = S·h1 ; h = relu(Z@W2) ; r = relu(h@A1+b1)@A2 + b2
    k_agg<<<gagg, 256>>>(bufB, bufA, n);
    readout_mma<<<mt, 256, MM_SMEM>>>(bufA, b1, b2, h_out, r_out, n);
}